// round 16
// baseline (speedup 1.0000x reference)
#include <cuda_runtime.h>

// Exact L-inf nearest neighbor in TWO kernels (self-restoring state):
//   bucket_k : bins B into fixed-K buckets (atomicAdd rank); overflow ->
//              global list every query also scans (extra candidates are
//              always sound).
//   fast_k   : 4 lanes/query, two chances (3x3 cells; +ring 2 / 5x5 wall
//              bound). Groups still failing are resolved IN-WARP: ballot,
//              then all 32 lanes brute-force the whole of B per failed
//              query (coalesced float4 SoA) -- unconditionally exact.
//              Last-ticket block zeroes g_cnt / g_ovf_cnt / ticket for the
//              next graph replay (all other blocks' reads already done).
// u64 pack (d_bits<<32 | payload), payload idx-major: u64 min IS the
// lexicographic (d, idx) compare -> exact jnp.argmin first-index ties.
// Wall soundness: out-of-range B points clamp into edge cells, so a wall
// touching the grid edge is dropped; every unscanned point lies strictly
// beyond a remaining wall (EPS-strict accept).

#define G      128
#define HALO   2
#define GH     (G + 2 * HALO)             // 132
#define NH     (GH * GH)                  // 17424
#define K      8
#define X0     (-4.5f)
#define EXT    9.0f
#define H      (EXT / (float)G)           // 0.0703125, binary exact
#define INVH   ((float)G / EXT)
#define EPS    1e-6f

__device__ int    g_cnt[NH];              // zero-init; re-zeroed by last block
__device__ float4 g_bkt[NH * K];
__device__ int    g_ovf_cnt;
__device__ float4 g_ovf[4096];
__device__ int    g_ticket;

__device__ __forceinline__ int cell_coord(float v) {
    int c = __float2int_rd((v - X0) * INVH);
    return min(max(c, 0), G - 1);
}

// lexicographic (d, payload) min across a lane group via 2x REDUX.SYNC
__device__ __forceinline__ unsigned long long
group_min(unsigned mask, unsigned long long best)
{
    unsigned db = (unsigned)(best >> 32), pb = (unsigned)best;
    unsigned dmin = __reduce_min_sync(mask, db);
    unsigned pmin = __reduce_min_sync(mask, (db == dmin) ? pb : 0xFFFFFFFFu);
    return (((unsigned long long)dmin) << 32) | pmin;
}

// ---------------- build ----------------
__global__ void __launch_bounds__(256)
bucket_k(const float* __restrict__ B, int N)
{
    int n = blockIdx.x * 256 + threadIdx.x;
    if (n >= N) return;
    float x = __ldg(&B[n]), y = __ldg(&B[N + n]);
    int h = (cell_coord(y) + HALO) * GH + (cell_coord(x) + HALO);
    int rank = atomicAdd(&g_cnt[h], 1);
    if (rank < K) {
        int pos = h * K + rank;
        unsigned pay = ((unsigned)n << 19) | (unsigned)pos;
        g_bkt[pos] = make_float4(x, y, __uint_as_float(pay), 0.0f);
    } else {
        int o = atomicAdd(&g_ovf_cnt, 1);
        unsigned pay = ((unsigned)n << 19) | (1u << 18) | (unsigned)o;
        g_ovf[o] = make_float4(x, y, __uint_as_float(pay), 0.0f);
    }
}

// ---------------- fast-path helpers ----------------
__device__ __forceinline__ void eval_pt(float4 pt, float ax, float ay,
                                        unsigned long long& best)
{
    float d = fmaxf(fabsf(ax - pt.x), fabsf(ay - pt.y));
    unsigned long long c = (((unsigned long long)__float_as_uint(d)) << 32)
                         | (unsigned long long)__float_as_uint(pt.z);
    best = min(best, c);
}

__device__ __forceinline__ void scan_hcell(int h, float ax, float ay,
                                           unsigned long long& best)
{
    int cnt = min(__ldg(&g_cnt[h]), K);
    const float4* bp = &g_bkt[h * K];
    for (int j = 0; j < cnt; ++j) eval_pt(__ldg(&bp[j]), ax, ay, best);
}

__device__ __forceinline__ float wall_bound(float ax, float ay,
                                            int cx, int cy, int r)
{
    float mb = __int_as_float(0x7f800000);
    if (cx - r > 0)     mb = fminf(mb, ax - (X0 + (float)(cx - r) * H));
    if (cx + r < G - 1) mb = fminf(mb, (X0 + (float)(cx + r + 1) * H) - ax);
    if (cy - r > 0)     mb = fminf(mb, ay - (X0 + (float)(cy - r) * H));
    if (cy + r < G - 1) mb = fminf(mb, (X0 + (float)(cy + r + 1) * H) - ay);
    return mb;
}

// ---------------- fast kernel: 4 lanes/query + in-warp tail -------------
__global__ void __launch_bounds__(256)
fast_k(const float* __restrict__ A, const float* __restrict__ B,
       float* __restrict__ out, int Q, int N)
{
    __shared__ int s_last;

    const int tid   = blockIdx.x * 256 + threadIdx.x;
    const int q     = tid >> 2;
    const int lane  = tid & 3;
    const int wlane = threadIdx.x & 31;
    const bool live = (q < Q);            // Q*4 is a multiple of 256 in
                                          // practice; guard stays for safety
    const unsigned gmask = 0xFu << (threadIdx.x & 28);

    float ax = 0.0f, ay = 0.0f;
    int cx = 0, cy = 0, hc = HALO * GH + HALO;
    if (live) {
        const float2 aq = __ldg(&((const float2*)A)[q]);
        ax = aq.x; ay = aq.y;
        cx = cell_coord(ax); cy = cell_coord(ay);
        hc = (cy + HALO) * GH + (cx + HALO);
    }

    unsigned long long best = 0xFFFFFFFFFFFFFFFFull;
    bool ok = true;

    if (live) {
        {   // chance 1: 3x3 cells, cell-per-lane
            int c1 = lane, c2 = lane + 4;
            int h1 = hc + (c1 / 3 - 1) * GH + (c1 % 3 - 1);
            int h2 = hc + (c2 / 3 - 1) * GH + (c2 % 3 - 1);
            scan_hcell(h1, ax, ay, best);
            scan_hcell(h2, ax, ay, best);
            if (lane == 0) scan_hcell(hc + GH + 1, ax, ay, best);
        }
        {   // overflow sweep (expected tiny)
            int oc = g_ovf_cnt;
            for (int o = lane; o < oc; o += 4)
                eval_pt(__ldg(&g_ovf[o]), ax, ay, best);
        }
        best = group_min(gmask, best);
        ok = __uint_as_float((unsigned)(best >> 32))
             <= wall_bound(ax, ay, cx, cy, 1) - EPS;

        if (!ok) {   // chance 2: ring 2 (16 cells, 4/lane)
            #pragma unroll
            for (int k = 0; k < 4; ++k) {
                int tc = lane * 4 + k;
                int di, dj;
                if (tc < 5)       { di = tc - 2; dj = -2; }
                else if (tc < 10) { di = tc - 7; dj =  2; }
                else { int t2 = tc - 10; dj = (t2 >> 1) - 1; di = (t2 & 1) ? 2 : -2; }
                scan_hcell(hc + dj * GH + di, ax, ay, best);
            }
            best = group_min(gmask, best);
            ok = __uint_as_float((unsigned)(best >> 32))
                 <= wall_bound(ax, ay, cx, cy, 2) - EPS;
        }

        if (ok && lane == 0) {
            unsigned pay = (unsigned)best;
            int pos = (int)(pay & 0x3FFFFu);
            float4 pt = (pay & (1u << 18)) ? __ldg(&g_ovf[pos])
                                           : __ldg(&g_bkt[pos]);
            ((float2*)out)[q] = make_float2(ax - pt.x, ay - pt.y);
        }
    }

    // ---- in-warp tail: whole warp brute-forces each failed query ----
    unsigned fmask = __ballot_sync(0xffffffffu, live && !ok);
    const float4* __restrict__ Bx4 = (const float4*)B;
    const float4* __restrict__ By4 = (const float4*)(B + N);
    const int Nv4 = ((N & 3) == 0) ? (N >> 2) : 0;   // float4 count (vec path)

    while (fmask) {
        int base = (__ffs(fmask) - 1) & ~3;
        fmask &= ~(0xFu << base);
        float fx = __shfl_sync(0xffffffffu, ax, base);
        float fy = __shfl_sync(0xffffffffu, ay, base);
        int   fq = __shfl_sync(0xffffffffu, q,  base);

        unsigned long long fb = 0xFFFFFFFFFFFFFFFFull;
        for (int i4 = wlane; i4 < Nv4; i4 += 32) {
            float4 xs = __ldg(&Bx4[i4]);
            float4 ys = __ldg(&By4[i4]);
            int n0 = i4 << 2;
            float d0 = fmaxf(fabsf(fx - xs.x), fabsf(fy - ys.x));
            float d1 = fmaxf(fabsf(fx - xs.y), fabsf(fy - ys.y));
            float d2 = fmaxf(fabsf(fx - xs.z), fabsf(fy - ys.z));
            float d3 = fmaxf(fabsf(fx - xs.w), fabsf(fy - ys.w));
            fb = min(fb, (((unsigned long long)__float_as_uint(d0)) << 32) | (unsigned)(n0));
            fb = min(fb, (((unsigned long long)__float_as_uint(d1)) << 32) | (unsigned)(n0 + 1));
            fb = min(fb, (((unsigned long long)__float_as_uint(d2)) << 32) | (unsigned)(n0 + 2));
            fb = min(fb, (((unsigned long long)__float_as_uint(d3)) << 32) | (unsigned)(n0 + 3));
        }
        for (int n = (Nv4 << 2) + wlane; n < N; n += 32) {
            float d = fmaxf(fabsf(fx - __ldg(&B[n])), fabsf(fy - __ldg(&B[N + n])));
            fb = min(fb, (((unsigned long long)__float_as_uint(d)) << 32) | (unsigned)n);
        }
        fb = group_min(0xffffffffu, fb);
        if (wlane == base) {
            int nb = (int)(fb & 0xFFFFFFFFu);
            ((float2*)out)[fq] = make_float2(fx - __ldg(&B[nb]),
                                             fy - __ldg(&B[N + nb]));
        }
    }

    // ---- last-ticket cleanup: restore state for the next graph replay ----
    __syncthreads();
    if (threadIdx.x == 0) {
        __threadfence();
        s_last = (atomicAdd(&g_ticket, 1) == (int)gridDim.x - 1);
    }
    __syncthreads();
    if (s_last) {
        int4 z = make_int4(0, 0, 0, 0);
        int4* c4 = (int4*)g_cnt;
        for (int i = threadIdx.x; i < NH / 4; i += 256) c4[i] = z;
        if (threadIdx.x == 0) { g_ovf_cnt = 0; g_ticket = 0; }
    }
}

extern "C" void kernel_launch(void* const* d_in, const int* in_sizes, int n_in,
                              void* d_out, int out_size)
{
    const float* A = (const float*)d_in[0];   // [Q, 2]
    const float* B = (const float*)d_in[1];   // [2, N]
    float*     out = (float*)d_out;           // [Q, 2]

    const int Q = in_sizes[0] / 2;
    const int N = in_sizes[1] / 2;

    bucket_k<<<(N + 255) / 256, 256>>>(B, N);
    fast_k<<<(Q * 4 + 255) / 256, 256>>>(A, B, out, Q, N);
}

// round 17
// speedup vs baseline: 1.2775x; 1.2775x over previous
#include <cuda_runtime.h>

// Exact L-inf nearest neighbor. 4 kernels (R14 structure, smem-cached tail):
//   zero_k   : zero per-cell counts + counters (fully parallel).
//   bucket_k : point -> fixed-K bucket via atomicAdd rank; overflow points
//              go to a global list every query also scans.
//   fast_k   : 4 lanes/query. Chance 1: 3x3 halo cells + ovf sweep + wall
//              bound. Chance 2: ring 2 + 5x5 bound. Failures compacted.
//   slow_k   : B CACHED IN SHARED per block (32KB), then one block per
//              failed query (grid-stride): 16 smem evals/thread, REDUX
//              reduce. Unconditionally exact (full scan, u64 d<<32|n min
//              = jnp.argmin first-index semantics).
// Wall soundness (fast path): out-of-range B points clamp into edge cells,
// so a wall touching the grid edge is dropped; every unscanned point lies
// strictly beyond a remaining wall (EPS-strict accept).

#define G      128
#define HALO   2
#define GH     (G + 2 * HALO)             // 132
#define NH     (GH * GH)                  // 17424
#define K      8
#define X0     (-4.5f)
#define EXT    9.0f
#define H      (EXT / (float)G)           // 0.0703125, binary exact
#define INVH   ((float)G / EXT)
#define EPS    1e-6f
#define SMAX   8192                       // max N cached in smem

__device__ int    g_cnt[NH];
__device__ float4 g_bkt[NH * K];          // (x, y, payload_bits, 0)
__device__ int    g_ovf_cnt;
__device__ float4 g_ovf[4096];
__device__ int    g_fail_cnt;
__device__ int    g_fail_q[32768];

__device__ __forceinline__ int cell_coord(float v) {
    int c = __float2int_rd((v - X0) * INVH);
    return min(max(c, 0), G - 1);
}

// lexicographic (d, payload) min across a lane group via 2x REDUX.SYNC
__device__ __forceinline__ unsigned long long
group_min(unsigned mask, unsigned long long best)
{
    unsigned db = (unsigned)(best >> 32), pb = (unsigned)best;
    unsigned dmin = __reduce_min_sync(mask, db);
    unsigned pmin = __reduce_min_sync(mask, (db == dmin) ? pb : 0xFFFFFFFFu);
    return (((unsigned long long)dmin) << 32) | pmin;
}

// ---------------- build ----------------
__global__ void __launch_bounds__(256)
zero_k()
{
    int i = blockIdx.x * 256 + threadIdx.x;
    if (i < NH) g_cnt[i] = 0;
    if (i == 0) { g_ovf_cnt = 0; g_fail_cnt = 0; }
}

__global__ void __launch_bounds__(256)
bucket_k(const float* __restrict__ B, int N)
{
    int n = blockIdx.x * 256 + threadIdx.x;
    if (n >= N) return;
    float x = __ldg(&B[n]), y = __ldg(&B[N + n]);
    int h = (cell_coord(y) + HALO) * GH + (cell_coord(x) + HALO);
    int rank = atomicAdd(&g_cnt[h], 1);
    if (rank < K) {
        int pos = h * K + rank;
        unsigned pay = ((unsigned)n << 19) | (unsigned)pos;
        g_bkt[pos] = make_float4(x, y, __uint_as_float(pay), 0.0f);
    } else {
        int o = atomicAdd(&g_ovf_cnt, 1);
        unsigned pay = ((unsigned)n << 19) | (1u << 18) | (unsigned)o;
        g_ovf[o] = make_float4(x, y, __uint_as_float(pay), 0.0f);
    }
}

// ---------------- fast-path helpers ----------------
__device__ __forceinline__ void eval_pt(float4 pt, float ax, float ay,
                                        unsigned long long& best)
{
    float d = fmaxf(fabsf(ax - pt.x), fabsf(ay - pt.y));
    unsigned long long c = (((unsigned long long)__float_as_uint(d)) << 32)
                         | (unsigned long long)__float_as_uint(pt.z);
    best = min(best, c);
}

__device__ __forceinline__ void scan_hcell(int h, float ax, float ay,
                                           unsigned long long& best)
{
    int cnt = min(__ldg(&g_cnt[h]), K);
    const float4* bp = &g_bkt[h * K];
    for (int j = 0; j < cnt; ++j) eval_pt(__ldg(&bp[j]), ax, ay, best);
}

__device__ __forceinline__ float wall_bound(float ax, float ay,
                                            int cx, int cy, int r)
{
    float mb = __int_as_float(0x7f800000);
    if (cx - r > 0)     mb = fminf(mb, ax - (X0 + (float)(cx - r) * H));
    if (cx + r < G - 1) mb = fminf(mb, (X0 + (float)(cx + r + 1) * H) - ax);
    if (cy - r > 0)     mb = fminf(mb, ay - (X0 + (float)(cy - r) * H));
    if (cy + r < G - 1) mb = fminf(mb, (X0 + (float)(cy + r + 1) * H) - ay);
    return mb;
}

// ---------------- fast kernel: 4 lanes/query ----------------
__global__ void __launch_bounds__(256, 8)
fast_k(const float* __restrict__ A, float* __restrict__ out, int Q)
{
    const int tid  = blockIdx.x * 256 + threadIdx.x;
    const int q    = tid >> 2;
    const int lane = tid & 3;
    if (q >= Q) return;

    const unsigned gmask = 0xFu << (threadIdx.x & 28);

    const float2 aq = __ldg(&((const float2*)A)[q]);
    const float ax = aq.x, ay = aq.y;
    const int cx = cell_coord(ax);
    const int cy = cell_coord(ay);
    const int hc = (cy + HALO) * GH + (cx + HALO);

    unsigned long long best = 0xFFFFFFFFFFFFFFFFull;

    {   // chance 1: 3x3 cells, cell-per-lane (halo -> no boundary branches)
        int c1 = lane, c2 = lane + 4;
        int h1 = hc + (c1 / 3 - 1) * GH + (c1 % 3 - 1);
        int h2 = hc + (c2 / 3 - 1) * GH + (c2 % 3 - 1);
        scan_hcell(h1, ax, ay, best);
        scan_hcell(h2, ax, ay, best);
        if (lane == 0) scan_hcell(hc + GH + 1, ax, ay, best);
    }
    {   // overflow sweep (expected tiny)
        int oc = g_ovf_cnt;
        for (int o = lane; o < oc; o += 4)
            eval_pt(__ldg(&g_ovf[o]), ax, ay, best);
    }
    best = group_min(gmask, best);

    bool ok = __uint_as_float((unsigned)(best >> 32))
              <= wall_bound(ax, ay, cx, cy, 1) - EPS;

    if (!ok) {   // chance 2: ring 2 (16 cells, 4/lane), then 5x5 bound
        #pragma unroll
        for (int k = 0; k < 4; ++k) {
            int tc = lane * 4 + k;
            int di, dj;
            if (tc < 5)       { di = tc - 2; dj = -2; }
            else if (tc < 10) { di = tc - 7; dj =  2; }
            else { int t2 = tc - 10; dj = (t2 >> 1) - 1; di = (t2 & 1) ? 2 : -2; }
            scan_hcell(hc + dj * GH + di, ax, ay, best);
        }
        best = group_min(gmask, best);
        ok = __uint_as_float((unsigned)(best >> 32))
             <= wall_bound(ax, ay, cx, cy, 2) - EPS;
    }

    if (lane == 0) {
        if (ok) {
            unsigned pay = (unsigned)best;
            int pos = (int)(pay & 0x3FFFFu);
            float4 pt = (pay & (1u << 18)) ? __ldg(&g_ovf[pos])
                                           : __ldg(&g_bkt[pos]);
            ((float2*)out)[q] = make_float2(ax - pt.x, ay - pt.y);
        } else {
            int slot = atomicAdd(&g_fail_cnt, 1);
            g_fail_q[slot] = q;
        }
    }
}

// ---------------- slow kernel: B in smem, block per failed query --------
__global__ void __launch_bounds__(256)
slow_k(const float* __restrict__ A, const float* __restrict__ B,
       float* __restrict__ out, int N)
{
    __shared__ float s_x[SMAX];
    __shared__ float s_y[SMAX];
    __shared__ unsigned long long s_best[8];

    const int cnt  = g_fail_cnt;
    const int t    = threadIdx.x;
    const int lane = t & 31;
    const int wid  = t >> 5;

    const bool cached = (N <= SMAX) && ((N & 3) == 0);

    if (cached) {
        // load B into shared once (coalesced float4)
        const float4* __restrict__ Bx4 = (const float4*)B;
        const float4* __restrict__ By4 = (const float4*)(B + N);
        for (int i4 = t; i4 < (N >> 2); i4 += 256) {
            ((float4*)s_x)[i4] = __ldg(&Bx4[i4]);
            ((float4*)s_y)[i4] = __ldg(&By4[i4]);
        }
    }
    __syncthreads();

    for (int f = blockIdx.x; f < cnt; f += gridDim.x) {
        __syncthreads();                           // s_best reuse guard
        const int q = g_fail_q[f];
        const float2 aq = __ldg(&((const float2*)A)[q]);
        const float ax = aq.x, ay = aq.y;

        unsigned long long best = 0xFFFFFFFFFFFFFFFFull;

        if (cached) {
            const int nv4 = N >> 2;
            for (int i4 = t; i4 < nv4; i4 += 256) {
                float4 xs = ((const float4*)s_x)[i4];
                float4 ys = ((const float4*)s_y)[i4];
                int n0 = i4 << 2;
                float d0 = fmaxf(fabsf(ax - xs.x), fabsf(ay - ys.x));
                float d1 = fmaxf(fabsf(ax - xs.y), fabsf(ay - ys.y));
                float d2 = fmaxf(fabsf(ax - xs.z), fabsf(ay - ys.z));
                float d3 = fmaxf(fabsf(ax - xs.w), fabsf(ay - ys.w));
                best = min(best, (((unsigned long long)__float_as_uint(d0)) << 32) | (unsigned)(n0));
                best = min(best, (((unsigned long long)__float_as_uint(d1)) << 32) | (unsigned)(n0 + 1));
                best = min(best, (((unsigned long long)__float_as_uint(d2)) << 32) | (unsigned)(n0 + 2));
                best = min(best, (((unsigned long long)__float_as_uint(d3)) << 32) | (unsigned)(n0 + 3));
            }
        } else {
            for (int n = t; n < N; n += 256) {
                float d = fmaxf(fabsf(ax - __ldg(&B[n])), fabsf(ay - __ldg(&B[N + n])));
                best = min(best, (((unsigned long long)__float_as_uint(d)) << 32) | (unsigned)n);
            }
        }

        best = group_min(0xffffffffu, best);
        if (lane == 0) s_best[wid] = best;
        __syncthreads();

        if (wid == 0) {
            best = (lane < 8) ? s_best[lane] : 0xFFFFFFFFFFFFFFFFull;
            best = group_min(0xffffffffu, best);
            if (lane == 0) {
                int nb = (int)(best & 0xFFFFFFFFu);
                ((float2*)out)[q] = make_float2(ax - __ldg(&B[nb]),
                                                ay - __ldg(&B[N + nb]));
            }
        }
    }
}

extern "C" void kernel_launch(void* const* d_in, const int* in_sizes, int n_in,
                              void* d_out, int out_size)
{
    const float* A = (const float*)d_in[0];   // [Q, 2]
    const float* B = (const float*)d_in[1];   // [2, N]
    float*     out = (float*)d_out;           // [Q, 2]

    const int Q = in_sizes[0] / 2;
    const int N = in_sizes[1] / 2;

    zero_k  <<<(NH + 255) / 256, 256>>>();
    bucket_k<<<(N + 255) / 256, 256>>>(B, N);

    fast_k<<<(Q * 4 + 255) / 256, 256>>>(A, out, Q);

    slow_k<<<512, 256>>>(A, B, out, N);
}